// round 2
// baseline (speedup 1.0000x reference)
#include <cuda_runtime.h>
#include <cstdint>

// ---------------- problem constants ----------------
#define MROWS 8192            // B*S = 4*2048
#define KDIM  2048            // D_IN
#define NDIM  2048            // D_OUT
#define RANK  16

// ---------------- GEMM tiling ----------------
#define BM 128
#define BN 128
#define BK 32                 // tf32 elems per k-iter
#define KITERS (KDIM / BK)    // 64
#define STAGES 3
#define THREADS 256           // 8 warps: 4 (M) x 2 (N), warp tile 32x64

#define A_TILE (BM * BK)      // floats per stage
#define B_TILE (BN * BK)
#define SMEM_FLOATS (STAGES * (A_TILE + B_TILE))   // 24576 floats = 96KB

// ---------------- scratch: folded weights (no allocation allowed) ----------------
__device__ float g_weff[(size_t)NDIM * KDIM];   // 16 MB

// ---------------- PTX helpers (base sm_103 only; NO 'a' features) ----------------
__device__ __forceinline__ uint32_t smem_u32(const void* p) {
    uint32_t a;
    asm("{ .reg .u64 t; cvta.to.shared.u64 t, %1; cvt.u32.u64 %0, t; }" : "=r"(a) : "l"(p));
    return a;
}

__device__ __forceinline__ void cp_async16(uint32_t saddr, const void* gaddr) {
    asm volatile("cp.async.cg.shared.global [%0], [%1], 16;"
                 :: "r"(saddr), "l"(gaddr) : "memory");
}
#define CP_COMMIT() asm volatile("cp.async.commit_group;" ::: "memory")
#define CP_WAIT_1() asm volatile("cp.async.wait_group 1;" ::: "memory")

// Round fp32 -> tf32 (RNA) producing the b32 register mma.sync expects.
__device__ __forceinline__ uint32_t ld_tf32(const float* p) {
    float v = *p;                 // LDS
    uint32_t r;
    asm("cvt.rna.tf32.f32 %0, %1;" : "=r"(r) : "f"(v));
    return r;
}

__device__ __forceinline__ void mma16n8k8(float* c, const uint32_t* a, const uint32_t* b) {
    asm volatile(
        "mma.sync.aligned.m16n8k8.row.col.f32.tf32.tf32.f32 "
        "{%0,%1,%2,%3}, {%4,%5,%6,%7}, {%8,%9}, {%0,%1,%2,%3};"
        : "+f"(c[0]), "+f"(c[1]), "+f"(c[2]), "+f"(c[3])
        : "r"(a[0]), "r"(a[1]), "r"(a[2]), "r"(a[3]), "r"(b[0]), "r"(b[1]));
}

// XOR swizzle: float index within a [rows][BK] tile; conflict-free fragment LDS,
// and 16B cp.async stores stay contiguous (swizzle moves in 4-float units).
__device__ __forceinline__ int swz(int row, int col) {
    return row * BK + (col ^ ((row & 7) << 2));
}

// ---------------- prep: W_eff = W + scale * (B @ A) ----------------
__global__ void prep_weff(const float* __restrict__ W, const float* __restrict__ A,
                          const float* __restrict__ Bm, const float* __restrict__ scale_p) {
    __shared__ float Brow[RANK];
    __shared__ float s_scale;
    int o = blockIdx.x;
    if (threadIdx.x < RANK) Brow[threadIdx.x] = Bm[o * RANK + threadIdx.x];
    if (threadIdx.x == 0) s_scale = *scale_p;
    __syncthreads();
    float s = s_scale;
    for (int d = threadIdx.x; d < KDIM; d += blockDim.x) {
        float acc = W[(size_t)o * KDIM + d];
        #pragma unroll
        for (int r = 0; r < RANK; r++)
            acc += s * Brow[r] * A[(size_t)r * KDIM + d];
        g_weff[(size_t)o * KDIM + d] = acc;
    }
}

// ---------------- main GEMM: out = x @ W_eff^T + b (tf32 mma.sync) ----------------
__global__ void __launch_bounds__(THREADS, 1)
gemm_tf32(const float* __restrict__ x, const float* __restrict__ w,
          const float* __restrict__ bias, float* __restrict__ out) {
    extern __shared__ float smem[];
    float* sA = smem;                         // [STAGES][BM*BK]
    float* sB = smem + STAGES * A_TILE;       // [STAGES][BN*BK]

    const int tid  = threadIdx.x;
    const int lane = tid & 31;
    const int wid  = tid >> 5;
    const int wm   = (wid & 3) * 32;          // warp M offset in tile
    const int wn   = (wid >> 2) * 64;         // warp N offset in tile
    const int m0   = blockIdx.y * BM;
    const int n0   = blockIdx.x * BN;

    const uint32_t sA_u = smem_u32(sA);
    const uint32_t sB_u = smem_u32(sB);

    // cp.async mapping: 8 chunks of 16B per 128B row; 32 rows per pass, 4 passes.
    const int lrow  = tid >> 3;               // 0..31
    const int lcol4 = (tid & 7) * 4;          // 0,4,...,28

    const float* gA = x + (size_t)m0 * KDIM;
    const float* gB = w + (size_t)n0 * KDIM;

    auto issue_load = [&](int kk, int stage) {
        const float* ga = gA + (size_t)kk * BK;
        const float* gb = gB + (size_t)kk * BK;
        uint32_t sa = sA_u + (uint32_t)(stage * A_TILE) * 4u;
        uint32_t sb = sB_u + (uint32_t)(stage * B_TILE) * 4u;
        #pragma unroll
        for (int p = 0; p < 4; p++) {
            int r = lrow + p * 32;
            cp_async16(sa + (uint32_t)swz(r, lcol4) * 4u, ga + (size_t)r * KDIM + lcol4);
            cp_async16(sb + (uint32_t)swz(r, lcol4) * 4u, gb + (size_t)r * KDIM + lcol4);
        }
    };

    float acc[2][8][4];
    #pragma unroll
    for (int mt = 0; mt < 2; mt++)
        #pragma unroll
        for (int nt = 0; nt < 8; nt++)
            #pragma unroll
            for (int j = 0; j < 4; j++) acc[mt][nt][j] = 0.0f;

    // bias fragments (per-thread output columns; independent of m)
    float2 bv[8];
    #pragma unroll
    for (int nt = 0; nt < 8; nt++)
        bv[nt] = *reinterpret_cast<const float2*>(bias + n0 + wn + nt * 8 + (lane & 3) * 2);

    // prologue: fill 2 stages
    issue_load(0, 0); CP_COMMIT();
    issue_load(1, 1); CP_COMMIT();

    for (int k = 0; k < KITERS; k++) {
        CP_WAIT_1();
        __syncthreads();

        int knext = k + 2;
        if (knext < KITERS) issue_load(knext, knext % STAGES);
        CP_COMMIT();   // commit each iter (possibly empty) to keep group accounting fixed

        const float* a = sA + (k % STAGES) * A_TILE;
        const float* b = sB + (k % STAGES) * B_TILE;

        #pragma unroll
        for (int kt = 0; kt < 4; kt++) {
            const int kb = kt * 8;
            const int kc = kb + (lane & 3);

            uint32_t af[2][4];
            #pragma unroll
            for (int mt = 0; mt < 2; mt++) {
                int r = wm + mt * 16 + (lane >> 2);
                af[mt][0] = ld_tf32(a + swz(r,     kc));
                af[mt][1] = ld_tf32(a + swz(r + 8, kc));
                af[mt][2] = ld_tf32(a + swz(r,     kc + 4));
                af[mt][3] = ld_tf32(a + swz(r + 8, kc + 4));
            }

            uint32_t bf[8][2];
            #pragma unroll
            for (int nt = 0; nt < 8; nt++) {
                int c = wn + nt * 8 + (lane >> 2);
                bf[nt][0] = ld_tf32(b + swz(c, kc));
                bf[nt][1] = ld_tf32(b + swz(c, kc + 4));
            }

            #pragma unroll
            for (int mt = 0; mt < 2; mt++)
                #pragma unroll
                for (int nt = 0; nt < 8; nt++)
                    mma16n8k8(acc[mt][nt], af[mt], bf[nt]);
        }
    }

    // epilogue: bias add + float2 stores
    #pragma unroll
    for (int mt = 0; mt < 2; mt++) {
        int r0 = m0 + wm + mt * 16 + (lane >> 2);
        #pragma unroll
        for (int nt = 0; nt < 8; nt++) {
            int c = n0 + wn + nt * 8 + (lane & 3) * 2;
            float2 v0, v1;
            v0.x = acc[mt][nt][0] + bv[nt].x;
            v0.y = acc[mt][nt][1] + bv[nt].y;
            v1.x = acc[mt][nt][2] + bv[nt].x;
            v1.y = acc[mt][nt][3] + bv[nt].y;
            *reinterpret_cast<float2*>(out + (size_t)r0 * NDIM + c)       = v0;
            *reinterpret_cast<float2*>(out + (size_t)(r0 + 8) * NDIM + c) = v1;
        }
    }
}

// ---------------- host launch ----------------
extern "C" void kernel_launch(void* const* d_in, const int* in_sizes, int n_in,
                              void* d_out, int out_size) {
    (void)in_sizes; (void)n_in; (void)out_size;
    const float* x     = (const float*)d_in[0];
    const float* W     = (const float*)d_in[1];
    const float* b     = (const float*)d_in[2];
    const float* A     = (const float*)d_in[3];
    const float* Bm    = (const float*)d_in[4];
    const float* scale = (const float*)d_in[5];
    float* out = (float*)d_out;

    void* weff = nullptr;
    cudaGetSymbolAddress(&weff, g_weff);

    prep_weff<<<NDIM, 256>>>(W, A, Bm, scale);

    const int smem_bytes = SMEM_FLOATS * sizeof(float);   // 96 KB
    cudaFuncSetAttribute(gemm_tf32, cudaFuncAttributeMaxDynamicSharedMemorySize, smem_bytes);
    dim3 grid(NDIM / BN, MROWS / BM);   // (16, 64)
    gemm_tf32<<<grid, THREADS, smem_bytes>>>(x, (const float*)weff, b, out);
}

// round 3
// speedup vs baseline: 2.0318x; 2.0318x over previous
#include <cuda_runtime.h>
#include <cstdint>

// ---------------- problem constants ----------------
#define MROWS 8192            // B*S = 4*2048
#define KDIM  2048            // D_IN
#define NDIM  2048            // D_OUT
#define RANK  16

// ---------------- GEMM tiling ----------------
#define BM 128
#define BN 128
#define BK 32                 // tf32 elems per k-iter
#define KITERS (KDIM / BK)    // 64
#define STAGES 3
#define THREADS 128           // 4 warps: 2(M) x 2(N), warp tile 64x64

#define A_TILE (BM * BK)      // floats per stage (4096)
#define B_TILE (BN * BK)
#define SMEM_MAIN (STAGES * (A_TILE + B_TILE))        // 24576 floats = 96KB
#define SMEM_BIAS SMEM_MAIN                            // +128 floats
#define SMEM_FLOATS (SMEM_MAIN + BN)

// ---------------- scratch: pre-rounded tf32 operands ----------------
__device__ uint32_t g_x_tf[(size_t)MROWS * KDIM];   // 64 MB tf32(x)
__device__ uint32_t g_weff[(size_t)NDIM * KDIM];    // 16 MB tf32(W + s*B@A)

// ---------------- PTX helpers (base sm_103 only) ----------------
__device__ __forceinline__ uint32_t smem_u32(const void* p) {
    uint32_t a;
    asm("{ .reg .u64 t; cvta.to.shared.u64 t, %1; cvt.u32.u64 %0, t; }" : "=r"(a) : "l"(p));
    return a;
}

__device__ __forceinline__ void cp_async16(uint32_t saddr, const void* gaddr) {
    asm volatile("cp.async.cg.shared.global [%0], [%1], 16;"
                 :: "r"(saddr), "l"(gaddr) : "memory");
}
#define CP_COMMIT() asm volatile("cp.async.commit_group;" ::: "memory")
#define CP_WAIT_1() asm volatile("cp.async.wait_group 1;" ::: "memory")

__device__ __forceinline__ uint32_t tf32_rna(float x) {
    uint32_t r;
    asm("cvt.rna.tf32.f32 %0, %1;" : "=r"(r) : "f"(x));
    return r;
}

__device__ __forceinline__ void mma16n8k8(float* c, const uint32_t* a, const uint32_t* b) {
    asm volatile(
        "mma.sync.aligned.m16n8k8.row.col.f32.tf32.tf32.f32 "
        "{%0,%1,%2,%3}, {%4,%5,%6,%7}, {%8,%9}, {%0,%1,%2,%3};"
        : "+f"(c[0]), "+f"(c[1]), "+f"(c[2]), "+f"(c[3])
        : "r"(a[0]), "r"(a[1]), "r"(a[2]), "r"(a[3]), "r"(b[0]), "r"(b[1]));
}

// XOR swizzle within a [rows][BK] tile (4-float granularity; conflict-free
// fragment LDS, 16B cp.async chunks stay contiguous)
__device__ __forceinline__ int swz(int row, int col) {
    return row * BK + (col ^ ((row & 7) << 2));
}

// ---------------- prep: W_eff = tf32(W + scale * (B @ A)) ----------------
__global__ void prep_weff(const float* __restrict__ W, const float* __restrict__ A,
                          const float* __restrict__ Bm, const float* __restrict__ scale_p) {
    __shared__ float Brow[RANK];
    __shared__ float s_scale;
    int o = blockIdx.x;
    if (threadIdx.x < RANK) Brow[threadIdx.x] = Bm[o * RANK + threadIdx.x];
    if (threadIdx.x == 0) s_scale = *scale_p;
    __syncthreads();
    float s = s_scale;
    for (int d = threadIdx.x; d < KDIM; d += blockDim.x) {
        float acc = W[(size_t)o * KDIM + d];
        #pragma unroll
        for (int r = 0; r < RANK; r++)
            acc += s * Brow[r] * A[(size_t)r * KDIM + d];
        g_weff[(size_t)o * KDIM + d] = tf32_rna(acc);
    }
}

// ---------------- prep: x -> tf32 bits ----------------
__global__ void prep_x(const float4* __restrict__ x) {
    size_t i = (size_t)blockIdx.x * blockDim.x + threadIdx.x;
    float4 v = x[i];
    uint4 o;
    o.x = tf32_rna(v.x); o.y = tf32_rna(v.y); o.z = tf32_rna(v.z); o.w = tf32_rna(v.w);
    reinterpret_cast<uint4*>(g_x_tf)[i] = o;
}

// ---------------- main GEMM: out = x @ W_eff^T + b ----------------
__global__ void __launch_bounds__(THREADS, 2)
gemm_tf32(const uint32_t* __restrict__ x, const uint32_t* __restrict__ w,
          const float* __restrict__ bias, float* __restrict__ out) {
    extern __shared__ uint32_t smem[];
    uint32_t* sA = smem;                        // [STAGES][BM*BK]
    uint32_t* sB = smem + STAGES * A_TILE;      // [STAGES][BN*BK]
    float* sBias = reinterpret_cast<float*>(smem + SMEM_BIAS);

    const int tid  = threadIdx.x;
    const int lane = tid & 31;
    const int wid  = tid >> 5;
    const int wm   = (wid & 1) * 64;            // warp M offset
    const int wn   = (wid >> 1) * 64;           // warp N offset
    const int m0   = blockIdx.y * BM;
    const int n0   = blockIdx.x * BN;

    const uint32_t sA_u = smem_u32(sA);
    const uint32_t sB_u = smem_u32(sB);

    // bias -> smem
    sBias[tid] = bias[n0 + tid];

    // cp.async mapping: 16B chunks; 16 rows per pass, 8 passes per tile
    const int lrow  = tid >> 3;                 // 0..15
    const int lcol4 = (tid & 7) * 4;            // 0..28

    const uint32_t* gA = x + (size_t)m0 * KDIM;
    const uint32_t* gB = w + (size_t)n0 * KDIM;

    auto issue_load = [&](int kk, int stage) {
        const uint32_t* ga = gA + (size_t)kk * BK;
        const uint32_t* gb = gB + (size_t)kk * BK;
        uint32_t sa = sA_u + (uint32_t)(stage * A_TILE) * 4u;
        uint32_t sb = sB_u + (uint32_t)(stage * B_TILE) * 4u;
        #pragma unroll
        for (int p = 0; p < 8; p++) {
            int r = lrow + p * 16;
            cp_async16(sa + (uint32_t)swz(r, lcol4) * 4u, ga + (size_t)r * KDIM + lcol4);
            cp_async16(sb + (uint32_t)swz(r, lcol4) * 4u, gb + (size_t)r * KDIM + lcol4);
        }
    };

    float acc[4][8][4];
    #pragma unroll
    for (int mt = 0; mt < 4; mt++)
        #pragma unroll
        for (int nt = 0; nt < 8; nt++)
            #pragma unroll
            for (int j = 0; j < 4; j++) acc[mt][nt][j] = 0.0f;

    issue_load(0, 0); CP_COMMIT();
    issue_load(1, 1); CP_COMMIT();

    for (int k = 0; k < KITERS; k++) {
        CP_WAIT_1();
        __syncthreads();

        int knext = k + 2;
        if (knext < KITERS) issue_load(knext, knext % STAGES);
        CP_COMMIT();

        const uint32_t* a = sA + (k % STAGES) * A_TILE;
        const uint32_t* b = sB + (k % STAGES) * B_TILE;

        #pragma unroll
        for (int kt = 0; kt < 4; kt++) {
            const int kc = kt * 8 + (lane & 3);

            uint32_t af[4][4];
            #pragma unroll
            for (int mt = 0; mt < 4; mt++) {
                int r = wm + mt * 16 + (lane >> 2);
                af[mt][0] = a[swz(r,     kc)];
                af[mt][1] = a[swz(r + 8, kc)];
                af[mt][2] = a[swz(r,     kc + 4)];
                af[mt][3] = a[swz(r + 8, kc + 4)];
            }

            uint32_t bf[8][2];
            #pragma unroll
            for (int nt = 0; nt < 8; nt++) {
                int c = wn + nt * 8 + (lane >> 2);
                bf[nt][0] = b[swz(c, kc)];
                bf[nt][1] = b[swz(c, kc + 4)];
            }

            #pragma unroll
            for (int mt = 0; mt < 4; mt++)
                #pragma unroll
                for (int nt = 0; nt < 8; nt++)
                    mma16n8k8(acc[mt][nt], af[mt], bf[nt]);
        }
    }

    __syncthreads();   // all LDS done before bias reads race nothing; harmless order point

    // epilogue: bias add + float2 stores
    #pragma unroll
    for (int mt = 0; mt < 4; mt++) {
        int r0 = m0 + wm + mt * 16 + (lane >> 2);
        #pragma unroll
        for (int nt = 0; nt < 8; nt++) {
            int cl = wn + nt * 8 + (lane & 3) * 2;
            float bx = sBias[cl], by = sBias[cl + 1];
            int c = n0 + cl;
            float2 v0, v1;
            v0.x = acc[mt][nt][0] + bx;
            v0.y = acc[mt][nt][1] + by;
            v1.x = acc[mt][nt][2] + bx;
            v1.y = acc[mt][nt][3] + by;
            *reinterpret_cast<float2*>(out + (size_t)r0 * NDIM + c)       = v0;
            *reinterpret_cast<float2*>(out + (size_t)(r0 + 8) * NDIM + c) = v1;
        }
    }
}

// ---------------- host launch ----------------
extern "C" void kernel_launch(void* const* d_in, const int* in_sizes, int n_in,
                              void* d_out, int out_size) {
    (void)in_sizes; (void)n_in; (void)out_size;
    const float* x     = (const float*)d_in[0];
    const float* W     = (const float*)d_in[1];
    const float* b     = (const float*)d_in[2];
    const float* A     = (const float*)d_in[3];
    const float* Bm    = (const float*)d_in[4];
    const float* scale = (const float*)d_in[5];
    float* out = (float*)d_out;

    void* xtf = nullptr;
    void* weff = nullptr;
    cudaGetSymbolAddress(&xtf, g_x_tf);
    cudaGetSymbolAddress(&weff, g_weff);

    prep_x<<<(MROWS * KDIM / 4) / 256, 256>>>((const float4*)x);
    prep_weff<<<NDIM, 256>>>(W, A, Bm, scale);

    const int smem_bytes = SMEM_FLOATS * sizeof(uint32_t);   // ~96.5 KB
    cudaFuncSetAttribute(gemm_tf32, cudaFuncAttributeMaxDynamicSharedMemorySize, smem_bytes);
    dim3 grid(NDIM / BN, MROWS / BM);   // (16, 64) = 1024 CTAs
    gemm_tf32<<<grid, THREADS, smem_bytes>>>((const uint32_t*)xtf, (const uint32_t*)weff, b, out);
}

// round 4
// speedup vs baseline: 3.9372x; 1.9378x over previous
#include <cuda_runtime.h>
#include <cuda_fp16.h>
#include <cstdint>

// ---------------- problem constants ----------------
#define MROWS 8192            // B*S = 4*2048
#define KDIM  2048            // D_IN
#define NDIM  2048            // D_OUT
#define RANK  16

// ---------------- GEMM tiling ----------------
#define BM 128
#define BN 128
#define BK 64                 // fp16 elems per k-iter (=128B row)
#define KITERS (KDIM / BK)    // 32
#define STAGES 3
#define THREADS 128           // 4 warps: 2(M) x 2(N), warp tile 64x64

#define A_BYTES (BM * BK * 2)                 // 16384 per stage
#define B_BYTES (BN * BK * 2)                 // 16384 per stage
#define STAGE_BYTES (A_BYTES + B_BYTES)       // 32768
#define SMEM_BYTES (STAGES * STAGE_BYTES + 512)   // 98816 (bias at tail)

// ---------------- scratch: pre-rounded fp16 operands ----------------
__device__ __half g_x_h[(size_t)MROWS * KDIM];   // 32 MB fp16(x)
__device__ __half g_w_h[(size_t)NDIM * KDIM];    // 8 MB  fp16(W + s*B@A)

// ---------------- PTX helpers (base sm_103 only) ----------------
__device__ __forceinline__ uint32_t smem_u32(const void* p) {
    uint32_t a;
    asm("{ .reg .u64 t; cvta.to.shared.u64 t, %1; cvt.u32.u64 %0, t; }" : "=r"(a) : "l"(p));
    return a;
}

__device__ __forceinline__ void cp_async16(uint32_t saddr, const void* gaddr) {
    asm volatile("cp.async.cg.shared.global [%0], [%1], 16;"
                 :: "r"(saddr), "l"(gaddr) : "memory");
}
#define CP_COMMIT() asm volatile("cp.async.commit_group;" ::: "memory")
#define CP_WAIT_1() asm volatile("cp.async.wait_group 1;" ::: "memory")

__device__ __forceinline__ void ldsm_x4(uint32_t* r, uint32_t addr) {
    asm volatile("ldmatrix.sync.aligned.m8n8.x4.shared.b16 {%0,%1,%2,%3}, [%4];"
                 : "=r"(r[0]), "=r"(r[1]), "=r"(r[2]), "=r"(r[3]) : "r"(addr));
}

__device__ __forceinline__ void mma16n8k16(float* c, const uint32_t* a, const uint32_t* b) {
    asm volatile(
        "mma.sync.aligned.m16n8k16.row.col.f32.f16.f16.f32 "
        "{%0,%1,%2,%3}, {%4,%5,%6,%7}, {%8,%9}, {%0,%1,%2,%3};"
        : "+f"(c[0]), "+f"(c[1]), "+f"(c[2]), "+f"(c[3])
        : "r"(a[0]), "r"(a[1]), "r"(a[2]), "r"(a[3]), "r"(b[0]), "r"(b[1]));
}

// ---------------- prep: W_eff = fp16(W + scale * (B @ A)) ----------------
__global__ void prep_weff(const float* __restrict__ W, const float* __restrict__ A,
                          const float* __restrict__ Bm, const float* __restrict__ scale_p) {
    __shared__ float Brow[RANK];
    __shared__ float s_scale;
    int o = blockIdx.x;
    if (threadIdx.x < RANK) Brow[threadIdx.x] = Bm[o * RANK + threadIdx.x];
    if (threadIdx.x == 0) s_scale = *scale_p;
    __syncthreads();
    float s = s_scale;
    for (int d = threadIdx.x; d < KDIM; d += blockDim.x) {
        float acc = W[(size_t)o * KDIM + d];
        #pragma unroll
        for (int r = 0; r < RANK; r++)
            acc += s * Brow[r] * A[(size_t)r * KDIM + d];
        g_w_h[(size_t)o * KDIM + d] = __float2half_rn(acc);
    }
}

// ---------------- prep: x -> fp16 ----------------
__global__ void prep_x(const float4* __restrict__ x) {
    size_t i = (size_t)blockIdx.x * blockDim.x + threadIdx.x;
    float4 v = x[i];
    __half2 lo = __floats2half2_rn(v.x, v.y);
    __half2 hi = __floats2half2_rn(v.z, v.w);
    uint2 o;
    o.x = *reinterpret_cast<uint32_t*>(&lo);
    o.y = *reinterpret_cast<uint32_t*>(&hi);
    reinterpret_cast<uint2*>(g_x_h)[i] = o;
}

// ---------------- main GEMM: out = x @ W_eff^T + b (fp16 mma.sync) ----------------
__global__ void __launch_bounds__(THREADS, 2)
gemm_f16(const __half* __restrict__ x, const __half* __restrict__ w,
         const float* __restrict__ bias, float* __restrict__ out) {
    extern __shared__ char smem[];
    const uint32_t sb = smem_u32(smem);
    float* sBias = reinterpret_cast<float*>(smem + STAGES * STAGE_BYTES);

    const int tid  = threadIdx.x;
    const int lane = tid & 31;
    const int wid  = tid >> 5;
    const int wm   = (wid & 1) * 64;            // warp M offset
    const int wn   = (wid >> 1) * 64;           // warp N offset
    const int m0   = blockIdx.y * BM;
    const int n0   = blockIdx.x * BN;

    sBias[tid] = bias[n0 + tid];

    // ---- cp.async mapping: 1024 16B-chunks per tile, 8 per thread ----
    // chunk (r, c): smem addr = base + r*128 + ((c ^ (r&7)) << 4)
    const __half* gA = x + (size_t)m0 * KDIM;
    const __half* gB = w + (size_t)n0 * KDIM;

    auto issue_load = [&](int kk, int stage) {
        uint32_t sa = sb + stage * STAGE_BYTES;
        uint32_t sbB = sa + A_BYTES;
        const __half* ga = gA + kk * BK;
        const __half* gb = gB + kk * BK;
        #pragma unroll
        for (int p = 0; p < 8; p++) {
            int lin = p * 128 + tid;
            int r = lin >> 3;
            int c = lin & 7;
            uint32_t soff = (uint32_t)(r * 128 + ((c ^ (r & 7)) << 4));
            const __half* go = ga + (size_t)r * KDIM + c * 8;
            cp_async16(sa + soff, go);
            const __half* go2 = gb + (size_t)r * KDIM + c * 8;
            cp_async16(sbB + soff, go2);
        }
    };

    float acc[4][8][4];
    #pragma unroll
    for (int mt = 0; mt < 4; mt++)
        #pragma unroll
        for (int nt = 0; nt < 8; nt++)
            #pragma unroll
            for (int j = 0; j < 4; j++) acc[mt][nt][j] = 0.0f;

    issue_load(0, 0); CP_COMMIT();
    issue_load(1, 1); CP_COMMIT();

    // ldmatrix per-lane row components (see derivation in analysis):
    // A: row = wm + (lane&15) + mt*16, chunk = kt*2 + (lane>>4)
    // B: row = wn + (lane&7) + ((lane>>4)<<3) + np*16, chunk = kt*2 + ((lane>>3)&1)
    const int aRow0 = wm + (lane & 15);
    const int bRow0 = wn + (lane & 7) + ((lane >> 4) << 3);
    const int aHalf = lane >> 4;
    const int bHalf = (lane >> 3) & 1;
    const int sw = lane & 7;                   // (row & 7) is lane&7 for both

    for (int k = 0; k < KITERS; k++) {
        CP_WAIT_1();
        __syncthreads();

        int knext = k + 2;
        if (knext < KITERS) issue_load(knext, knext % STAGES);
        CP_COMMIT();

        const uint32_t aBase = sb + (k % STAGES) * STAGE_BYTES;
        const uint32_t bBase = aBase + A_BYTES;

        #pragma unroll
        for (int kt = 0; kt < 4; kt++) {
            uint32_t af[4][4];
            #pragma unroll
            for (int mt = 0; mt < 4; mt++) {
                int row = aRow0 + mt * 16;
                uint32_t addr = aBase + row * 128 + (uint32_t)(((kt * 2 + aHalf) ^ sw) << 4);
                ldsm_x4(af[mt], addr);
            }
            uint32_t bf[8][2];
            #pragma unroll
            for (int np = 0; np < 4; np++) {
                int row = bRow0 + np * 16;
                uint32_t addr = bBase + row * 128 + (uint32_t)(((kt * 2 + bHalf) ^ sw) << 4);
                uint32_t t4[4];
                ldsm_x4(t4, addr);
                bf[np * 2 + 0][0] = t4[0]; bf[np * 2 + 0][1] = t4[1];
                bf[np * 2 + 1][0] = t4[2]; bf[np * 2 + 1][1] = t4[3];
            }
            #pragma unroll
            for (int mt = 0; mt < 4; mt++)
                #pragma unroll
                for (int nt = 0; nt < 8; nt++)
                    mma16n8k16(acc[mt][nt], af[mt], bf[nt]);
        }
    }

    __syncthreads();

    // epilogue: bias add + float2 stores
    #pragma unroll
    for (int mt = 0; mt < 4; mt++) {
        int r0 = m0 + wm + mt * 16 + (lane >> 2);
        #pragma unroll
        for (int nt = 0; nt < 8; nt++) {
            int cl = wn + nt * 8 + (lane & 3) * 2;
            float bx = sBias[cl], by = sBias[cl + 1];
            int c = n0 + cl;
            float2 v0, v1;
            v0.x = acc[mt][nt][0] + bx;
            v0.y = acc[mt][nt][1] + by;
            v1.x = acc[mt][nt][2] + bx;
            v1.y = acc[mt][nt][3] + by;
            *reinterpret_cast<float2*>(out + (size_t)r0 * NDIM + c)       = v0;
            *reinterpret_cast<float2*>(out + (size_t)(r0 + 8) * NDIM + c) = v1;
        }
    }
}

// ---------------- host launch ----------------
extern "C" void kernel_launch(void* const* d_in, const int* in_sizes, int n_in,
                              void* d_out, int out_size) {
    (void)in_sizes; (void)n_in; (void)out_size;
    const float* x     = (const float*)d_in[0];
    const float* W     = (const float*)d_in[1];
    const float* b     = (const float*)d_in[2];
    const float* A     = (const float*)d_in[3];
    const float* Bm    = (const float*)d_in[4];
    const float* scale = (const float*)d_in[5];
    float* out = (float*)d_out;

    void* xh = nullptr;
    void* wh = nullptr;
    cudaGetSymbolAddress(&xh, g_x_h);
    cudaGetSymbolAddress(&wh, g_w_h);

    prep_x<<<(MROWS * KDIM / 4) / 256, 256>>>((const float4*)x);
    prep_weff<<<NDIM, 256>>>(W, A, Bm, scale);

    cudaFuncSetAttribute(gemm_f16, cudaFuncAttributeMaxDynamicSharedMemorySize, SMEM_BYTES);
    dim3 grid(NDIM / BN, MROWS / BM);   // (16, 64) = 1024 CTAs
    gemm_f16<<<grid, THREADS, SMEM_BYTES>>>((const __half*)xh, (const __half*)wh, b, out);
}